// round 12
// baseline (speedup 1.0000x reference)
#include <cuda_runtime.h>

// MaxPool 2x2 stride 2, (16,64,512,512) fp32 -> (16,64,256,256) fp32.
// FINAL. DRAM-interface-bound streaming kernel at the measured GB300 ceiling
// for a 4:1 mixed read/write stream: 7240-7305 GB/s (91-92% of 8TB/s spec).
// Best harness measurement of the session: 186.14us (this exact config).
//
// One thread -> one float4 output (4 pooled values) via 4x coalesced LDG.128
// (__ldcg: L2-only, stream-once data never re-hits L1) + 1x STG.128.
// 64-thread CTAs (262,144 blocks): many tiny CTAs let the HW rasterizer
// provide free, deep memory-level parallelism (measured far better than a
// persistent grid: 204.9us).
//
// Session evidence — all measured on GB300, all other axes noise or worse:
//   layouts: per-thread f4 / f2-out coalesce / warp-row-pair MLP8 -> 186.3-186.8us
//   64B/thread spread loads -> 188.4us (wavefront inflation, L1 70%)
//   __stcs/__ldcs hints     -> neutral (L2 policy not binding)
//   persistent 1-wave grid  -> 204.9us (occupancy + load serialization loss)
//   CTA grain 256/128/64    -> all 91.3-92.2% DRAM (noise-equivalent)
// Compute pipes <7% busy; remaining ~8% gap to spec = DRAM bus turnaround/
// refresh, unreachable from SASS.

#define IN_H 512
#define OUT_H 256
#define BC (16 * 64)

#define IN_ROW_F4 128   // 512 floats / 4
#define OUT_ROW_F4 64   // 256 floats / 4

__global__ void maxpool2x2_kernel(const float4* __restrict__ in4,
                                  float4* __restrict__ out4) {
    unsigned tid = blockIdx.x * blockDim.x + threadIdx.x;

    unsigned ox4  = tid & (OUT_ROW_F4 - 1);         // [0, 64)
    unsigned rest = tid >> 6;
    unsigned oy   = rest & (OUT_H - 1);             // [0, 256)
    unsigned bc   = rest >> 8;                      // [0, 1024)

    unsigned ibase = bc * (IN_H * IN_ROW_F4) + (oy * 2) * IN_ROW_F4 + ox4 * 2;

    float4 r0a = __ldcg(&in4[ibase]);
    float4 r0b = __ldcg(&in4[ibase + 1]);
    float4 r1a = __ldcg(&in4[ibase + IN_ROW_F4]);
    float4 r1b = __ldcg(&in4[ibase + IN_ROW_F4 + 1]);

    float4 o;
    o.x = fmaxf(fmaxf(r0a.x, r0a.y), fmaxf(r1a.x, r1a.y));
    o.y = fmaxf(fmaxf(r0a.z, r0a.w), fmaxf(r1a.z, r1a.w));
    o.z = fmaxf(fmaxf(r0b.x, r0b.y), fmaxf(r1b.x, r1b.y));
    o.w = fmaxf(fmaxf(r0b.z, r0b.w), fmaxf(r1b.z, r1b.w));

    out4[tid] = o;
}

extern "C" void kernel_launch(void* const* d_in, const int* in_sizes, int n_in,
                              void* d_out, int out_size) {
    const float4* in4 = (const float4*)d_in[0];
    float4* out4 = (float4*)d_out;

    const unsigned total = (unsigned)BC * OUT_H * OUT_ROW_F4;  // 16,777,216
    const int threads = 64;
    const unsigned blocks = total / threads;                   // 262,144

    maxpool2x2_kernel<<<blocks, threads>>>(in4, out4);
}

// round 13
// speedup vs baseline: 1.0007x; 1.0007x over previous
#include <cuda_runtime.h>

// MaxPool 2x2 stride 2, (16,64,512,512) fp32 -> (16,64,256,256) fp32.
// DRAM-ceiling streaming kernel, LDG.E.256 variant (sm_100+ ld.global.v8.f32):
// each thread loads its 2x2-pool source as TWO 256-bit loads (one per input
// row, 32B contiguous per lane -> 1024B fully-contiguous warp wavefronts,
// 8 lines @100% utilization) instead of four LDG.128. Halves LSU issue and
// L1tex queue entries per byte. Output: one STG.128 per thread (R1 mapping).

#define IN_H 512
#define OUT_H 256
#define BC (16 * 64)

#define IN_ROW_F4 128   // 512 floats / 4
#define OUT_ROW_F4 64   // 256 floats / 4

__device__ __forceinline__ void ldg256(const float4* p, float4& lo, float4& hi) {
    asm volatile(
        "ld.global.nc.v8.f32 {%0, %1, %2, %3, %4, %5, %6, %7}, [%8];"
        : "=f"(lo.x), "=f"(lo.y), "=f"(lo.z), "=f"(lo.w),
          "=f"(hi.x), "=f"(hi.y), "=f"(hi.z), "=f"(hi.w)
        : "l"(p));
}

__global__ void maxpool2x2_kernel(const float4* __restrict__ in4,
                                  float4* __restrict__ out4) {
    unsigned tid = blockIdx.x * blockDim.x + threadIdx.x;

    unsigned ox4  = tid & (OUT_ROW_F4 - 1);         // [0, 64)
    unsigned rest = tid >> 6;
    unsigned oy   = rest & (OUT_H - 1);             // [0, 256)
    unsigned bc   = rest >> 8;                      // [0, 1024)

    // ibase is even -> 32B-aligned address for 256-bit loads.
    unsigned ibase = bc * (IN_H * IN_ROW_F4) + (oy * 2) * IN_ROW_F4 + ox4 * 2;

    float4 r0a, r0b, r1a, r1b;
    ldg256(&in4[ibase], r0a, r0b);
    ldg256(&in4[ibase + IN_ROW_F4], r1a, r1b);

    float4 o;
    o.x = fmaxf(fmaxf(r0a.x, r0a.y), fmaxf(r1a.x, r1a.y));
    o.y = fmaxf(fmaxf(r0a.z, r0a.w), fmaxf(r1a.z, r1a.w));
    o.z = fmaxf(fmaxf(r0b.x, r0b.y), fmaxf(r1b.x, r1b.y));
    o.w = fmaxf(fmaxf(r0b.z, r0b.w), fmaxf(r1b.z, r1b.w));

    out4[tid] = o;
}

extern "C" void kernel_launch(void* const* d_in, const int* in_sizes, int n_in,
                              void* d_out, int out_size) {
    const float4* in4 = (const float4*)d_in[0];
    float4* out4 = (float4*)d_out;

    const unsigned total = (unsigned)BC * OUT_H * OUT_ROW_F4;  // 16,777,216
    const int threads = 128;
    const unsigned blocks = total / threads;                   // 131,072

    maxpool2x2_kernel<<<blocks, threads>>>(in4, out4);
}